// round 11
// baseline (speedup 1.0000x reference)
#include <cuda_runtime.h>
#include <cuda_fp16.h>
#include <math.h>

#define NN 100000
#define NE 1600000
#define BB 2

typedef unsigned long long u64;

// ---------------- constant weights (16B aligned for f32x2 pair reads) ----------------
__constant__ __align__(16) float c_msg_w1[24*16];
__constant__ __align__(16) float c_msg_b1[16];
__constant__ __align__(16) float c_msg_w2[16*24];
__constant__ __align__(16) float c_msg_b2[24];
__constant__ __align__(16) float c_att_w1[8*16];
__constant__ __align__(16) float c_att_b1[16];
__constant__ __align__(16) float c_att_w2[16*32];
__constant__ __align__(16) float c_att_b2[32];
__constant__ __align__(16) float c_upd_w1[24*16];
__constant__ __align__(16) float c_upd_b1[16];
__constant__ __align__(16) float c_upd_w2[16*8];
__constant__ __align__(16) float c_upd_b2[8];

// ---------------- scratch ----------------
// NODE-MAJOR fp16 records: g_src[node*8 + batch*4 + chunk] (uint4 chunks).
// One 128B line per node-side covers BOTH batches -> a single gather serves
// the edge in both batches (4 -> 2 sectors per edge-unit).
// chunks: 0 Pa[0:8], 1 Pa[8:16], 2 a_query, 3 a_key   (src side)
//         0 Pb[0:8], 1 Pb[8:16], 2 b_key,   3 b_query (tgt side)
__device__ uint4 g_src[(size_t)NN*8];
__device__ uint4 g_tgt[(size_t)NN*8];
__device__ float4 g_numA[(size_t)BB*NN*2];
__device__ float4 g_numB[(size_t)BB*NN*2];
__device__ float  g_denA[(size_t)BB*NN];
__device__ float  g_denB[(size_t)BB*NN];

// ---------------- helpers ----------------
__device__ __forceinline__ u64 pack2(float a, float b) {
    u64 r; asm("mov.b64 %0, {%1, %2};" : "=l"(r) : "f"(a), "f"(b)); return r;
}
__device__ __forceinline__ u64 bcast2(float a) { return pack2(a, a); }
__device__ __forceinline__ void unpack2(u64 v, float& a, float& b) {
    asm("mov.b64 {%0, %1}, %2;" : "=f"(a), "=f"(b) : "l"(v));
}
__device__ __forceinline__ u64 fma2(u64 a, u64 b, u64 c) {
    u64 d; asm("fma.rn.f32x2 %0, %1, %2, %3;" : "=l"(d) : "l"(a), "l"(b), "l"(c)); return d;
}
__device__ __forceinline__ float fast_tanh(float x) {
    float y; asm("tanh.approx.f32 %0, %1;" : "=f"(y) : "f"(x)); return y;
}
// Branchless soft_clamp: 1e6*tanh(v*1e-6) ~= v - v*t^2/3 (t=v*1e-6); rel err <1e-13 here.
__device__ __forceinline__ float softclamp(float v) {
    float t = v * 1e-6f;
    return fmaf(-t * t * (1.0f/3.0f), v, v);
}
__device__ __forceinline__ unsigned h2pack(float a, float b) {
    __half2 h = __floats2half2_rn(a, b);
    return *reinterpret_cast<const unsigned*>(&h);
}
__device__ __forceinline__ float2 h2unpack(unsigned u) {
    __half2 h = *reinterpret_cast<const __half2*>(&u);
    return __half22float2(h);
}

// ================= kernel A: per-node precompute (scalar fp32) + fp16 pack =================
__global__ __launch_bounds__(256) void node_pre(const float* __restrict__ nodes) {
    int n = blockIdx.x * blockDim.x + threadIdx.x;
    if (n >= NN) return;
    int b = blockIdx.y;
    size_t idx = (size_t)b * NN + n;

    float x[8];
    float4 v0 = __ldg((const float4*)(nodes + idx*8));
    float4 v1 = __ldg((const float4*)(nodes + idx*8) + 1);
    x[0]=v0.x; x[1]=v0.y; x[2]=v0.z; x[3]=v0.w;
    x[4]=v1.x; x[5]=v1.y; x[6]=v1.z; x[7]=v1.w;

    float pa[16], pb[16], h[16];
#pragma unroll
    for (int j = 0; j < 16; j++) { pa[j] = c_msg_b1[j]; pb[j] = 0.f; h[j] = c_att_b1[j]; }
#pragma unroll
    for (int i = 0; i < 8; i++) {
#pragma unroll
        for (int j = 0; j < 16; j++) {
            pa[j] = fmaf(x[i], c_msg_w1[i*16 + j],     pa[j]);
            pb[j] = fmaf(x[i], c_msg_w1[(8+i)*16 + j], pb[j]);
            h[j]  = fmaf(x[i], c_att_w1[i*16 + j],     h[j]);
        }
    }
#pragma unroll
    for (int j = 0; j < 16; j++) h[j] = fast_tanh(h[j]);

    float att[32];
#pragma unroll
    for (int j = 0; j < 32; j++) att[j] = c_att_b2[j];
#pragma unroll
    for (int i = 0; i < 16; i++)
#pragma unroll
        for (int j = 0; j < 32; j++) att[j] = fmaf(h[i], c_att_w2[i*32 + j], att[j]);

    // att layout (jnp.split): a_key[0:8] a_query[8:16] b_key[16:24] b_query[24:32]
    // NODE-MAJOR write: [node][batch][chunk]
    uint4* sr = g_src + (size_t)n*8 + b*4;
    sr[0] = make_uint4(h2pack(pa[0],pa[1]),  h2pack(pa[2],pa[3]),
                       h2pack(pa[4],pa[5]),  h2pack(pa[6],pa[7]));
    sr[1] = make_uint4(h2pack(pa[8],pa[9]),  h2pack(pa[10],pa[11]),
                       h2pack(pa[12],pa[13]),h2pack(pa[14],pa[15]));
    sr[2] = make_uint4(h2pack(att[8],att[9]),  h2pack(att[10],att[11]),
                       h2pack(att[12],att[13]),h2pack(att[14],att[15]));   // a_query
    sr[3] = make_uint4(h2pack(att[0],att[1]),  h2pack(att[2],att[3]),
                       h2pack(att[4],att[5]),  h2pack(att[6],att[7]));     // a_key

    uint4* tr = g_tgt + (size_t)n*8 + b*4;
    tr[0] = make_uint4(h2pack(pb[0],pb[1]),  h2pack(pb[2],pb[3]),
                       h2pack(pb[4],pb[5]),  h2pack(pb[6],pb[7]));
    tr[1] = make_uint4(h2pack(pb[8],pb[9]),  h2pack(pb[10],pb[11]),
                       h2pack(pb[12],pb[13]),h2pack(pb[14],pb[15]));
    tr[2] = make_uint4(h2pack(att[16],att[17]),h2pack(att[18],att[19]),
                       h2pack(att[20],att[21]),h2pack(att[22],att[23]));   // b_key
    tr[3] = make_uint4(h2pack(att[24],att[25]),h2pack(att[26],att[27]),
                       h2pack(att[28],att[29]),h2pack(att[30],att[31]));   // b_query

    g_denA[idx] = 0.f;
    g_denB[idx] = 0.f;
    float4 z = make_float4(0.f, 0.f, 0.f, 0.f);
    g_numA[idx*2]   = z; g_numA[idx*2+1] = z;
    g_numB[idx*2]   = z; g_numB[idx*2+1] = z;
}

// ================= kernel B: edge pass, both batches per thread =================
// Staging fetches each node-side's 128B (both batches) ONCE and serves both
// batch-units: gather 2 sectors/unit. 8 iters: 8 lanes x 4 records per iter.
// smem stride 9 uint4: STS phase writes chunks 0-7 of one record (banks
// 0,4..28), LDS phase reads lane*9 stride (banks lane*36%32) — conflict-free.
__global__ __launch_bounds__(128) void edge_pass(const float* __restrict__ edges,
                                                 const int* __restrict__ srcs,
                                                 const int* __restrict__ tgts,
                                                 float* __restrict__ out_edges) {
    const unsigned FULL = 0xffffffffu;
    __shared__ uint4 st_src[4][32*9];
    __shared__ uint4 st_tgt[4][32*9];

    int w    = threadIdx.x >> 5;
    int lane = threadIdx.x & 31;
    int e    = blockIdx.x * 128 + w * 32 + lane;   // NE % 128 == 0

    int s = __ldg(srcs + e);
    int t = __ldg(tgts + e);

    // ---- cooperative staging: 8 iters x 4 records/side, 8 chunks each ----
    int c8  = lane & 7;           // chunk owned by this lane
    int sub = lane >> 3;          // which of 4 records this iteration
#pragma unroll
    for (int g = 0; g < 8; g++) {
        int rec = g*4 + sub;
        int sg = __shfl_sync(FULL, s, rec);
        int tg = __shfl_sync(FULL, t, rec);
        st_src[w][rec*9 + c8] = __ldg(g_src + (size_t)sg*8 + c8);
        st_tgt[w][rec*9 + c8] = __ldg(g_tgt + (size_t)tg*8 + c8);
    }
    __syncwarp();

#pragma unroll 1
    for (int b = 0; b < BB; b++) {
        uint4 s0 = st_src[w][lane*9 + b*4 + 0];
        uint4 s1 = st_src[w][lane*9 + b*4 + 1];
        uint4 s2 = st_src[w][lane*9 + b*4 + 2];
        uint4 s3 = st_src[w][lane*9 + b*4 + 3];
        uint4 t0 = st_tgt[w][lane*9 + b*4 + 0];
        uint4 t1 = st_tgt[w][lane*9 + b*4 + 1];
        uint4 t2 = st_tgt[w][lane*9 + b*4 + 2];
        uint4 t3 = st_tgt[w][lane*9 + b*4 + 3];

        // h init = Pa[src] + Pb[tgt]
        u64 hp[8];
        {
            float2 a, c2;
            a = h2unpack(s0.x); c2 = h2unpack(t0.x); hp[0] = pack2(a.x+c2.x, a.y+c2.y);
            a = h2unpack(s0.y); c2 = h2unpack(t0.y); hp[1] = pack2(a.x+c2.x, a.y+c2.y);
            a = h2unpack(s0.z); c2 = h2unpack(t0.z); hp[2] = pack2(a.x+c2.x, a.y+c2.y);
            a = h2unpack(s0.w); c2 = h2unpack(t0.w); hp[3] = pack2(a.x+c2.x, a.y+c2.y);
            a = h2unpack(s1.x); c2 = h2unpack(t1.x); hp[4] = pack2(a.x+c2.x, a.y+c2.y);
            a = h2unpack(s1.y); c2 = h2unpack(t1.y); hp[5] = pack2(a.x+c2.x, a.y+c2.y);
            a = h2unpack(s1.z); c2 = h2unpack(t1.z); hp[6] = pack2(a.x+c2.x, a.y+c2.y);
            a = h2unpack(s1.w); c2 = h2unpack(t1.w); hp[7] = pack2(a.x+c2.x, a.y+c2.y);
        }

        // logits
        float la = 0.f, lb = 0.f;
        {
            float2 q, k;
            q = h2unpack(s2.x); k = h2unpack(t2.x); la += q.x*k.x + q.y*k.y;
            q = h2unpack(s2.y); k = h2unpack(t2.y); la += q.x*k.x + q.y*k.y;
            q = h2unpack(s2.z); k = h2unpack(t2.z); la += q.x*k.x + q.y*k.y;
            q = h2unpack(s2.w); k = h2unpack(t2.w); la += q.x*k.x + q.y*k.y;
            q = h2unpack(t3.x); k = h2unpack(s3.x); lb += q.x*k.x + q.y*k.y;
            q = h2unpack(t3.y); k = h2unpack(s3.y); lb += q.x*k.x + q.y*k.y;
            q = h2unpack(t3.z); k = h2unpack(s3.z); lb += q.x*k.x + q.y*k.y;
            q = h2unpack(t3.w); k = h2unpack(s3.w); lb += q.x*k.x + q.y*k.y;
        }
        const float scale = 0.3535533905932738f; // 1/sqrt(8)
        float exa = __expf(la * scale);
        float exb = __expf(lb * scale);

        // edge features
        size_t eoff = ((size_t)b*NE + e)*8;
        float4 e0 = __ldg((const float4*)(edges + eoff));
        float4 e1 = __ldg((const float4*)(edges + eoff) + 1);
        float x[8] = {e0.x, e0.y, e0.z, e0.w, e1.x, e1.y, e1.z, e1.w};

        // layer 1 (f32x2)
        const u64* w1p = (const u64*)c_msg_w1;
#pragma unroll
        for (int i = 0; i < 8; i++) {
            u64 xb = bcast2(x[i]);
#pragma unroll
            for (int j = 0; j < 8; j++)
                hp[j] = fma2(xb, w1p[(16+i)*8 + j], hp[j]);
        }
        float h[16];
#pragma unroll
        for (int j = 0; j < 8; j++) { unpack2(hp[j], h[2*j], h[2*j+1]); }
#pragma unroll
        for (int j = 0; j < 16; j++) h[j] = fast_tanh(h[j]);

        // layer 2 (f32x2)
        const u64* w2p = (const u64*)c_msg_w2;
        u64 yp[12];
#pragma unroll
        for (int k = 0; k < 12; k++) yp[k] = ((const u64*)c_msg_b2)[k];
#pragma unroll
        for (int i = 0; i < 16; i++) {
            u64 hb = bcast2(h[i]);
#pragma unroll
            for (int k = 0; k < 12; k++) yp[k] = fma2(hb, w2p[i*12 + k], yp[k]);
        }
        float y[24];
#pragma unroll
        for (int k = 0; k < 12; k++) { unpack2(yp[k], y[2*k], y[2*k+1]); }

        // new_edges = soft_clamp(edges + m_ab)
        float4 o0 = make_float4(softclamp(x[0]+y[16]), softclamp(x[1]+y[17]),
                                softclamp(x[2]+y[18]), softclamp(x[3]+y[19]));
        float4 o1 = make_float4(softclamp(x[4]+y[20]), softclamp(x[5]+y[21]),
                                softclamp(x[6]+y[22]), softclamp(x[7]+y[23]));
        ((float4*)(out_edges + eoff))[0] = o0;
        ((float4*)(out_edges + eoff))[1] = o1;

        size_t si = (size_t)b*NN + s;
        size_t ti = (size_t)b*NN + t;
        atomicAdd(&g_denA[si], exa);
        atomicAdd(&g_denB[ti], exb);
        atomicAdd(&g_numA[si*2],   make_float4(exa*y[0], exa*y[1], exa*y[2],  exa*y[3]));
        atomicAdd(&g_numA[si*2+1], make_float4(exa*y[4], exa*y[5], exa*y[6],  exa*y[7]));
        atomicAdd(&g_numB[ti*2],   make_float4(exb*y[8], exb*y[9], exb*y[10], exb*y[11]));
        atomicAdd(&g_numB[ti*2+1], make_float4(exb*y[12],exb*y[13],exb*y[14], exb*y[15]));
    }
}

// ================= kernel C: node update (scalar fp32) =================
__global__ __launch_bounds__(256) void node_post(const float* __restrict__ nodes,
                                                 float* __restrict__ out_nodes) {
    int n = blockIdx.x * blockDim.x + threadIdx.x;
    if (n >= NN) return;
    size_t idx = (size_t)blockIdx.y * NN + n;

    float x[24];
    float4 v0 = __ldg((const float4*)(nodes + idx*8));
    float4 v1 = __ldg((const float4*)(nodes + idx*8) + 1);
    x[0]=v0.x; x[1]=v0.y; x[2]=v0.z; x[3]=v0.w;
    x[4]=v1.x; x[5]=v1.y; x[6]=v1.z; x[7]=v1.w;

    float ia = 1.f / (g_denA[idx] + 1e-10f);
    float4 na0 = g_numA[idx*2], na1 = g_numA[idx*2+1];
    x[8]=na0.x*ia;  x[9]=na0.y*ia;  x[10]=na0.z*ia; x[11]=na0.w*ia;
    x[12]=na1.x*ia; x[13]=na1.y*ia; x[14]=na1.z*ia; x[15]=na1.w*ia;

    float ib = 1.f / (g_denB[idx] + 1e-10f);
    float4 nb0 = g_numB[idx*2], nb1 = g_numB[idx*2+1];
    x[16]=nb0.x*ib; x[17]=nb0.y*ib; x[18]=nb0.z*ib; x[19]=nb0.w*ib;
    x[20]=nb1.x*ib; x[21]=nb1.y*ib; x[22]=nb1.z*ib; x[23]=nb1.w*ib;

    float h[16];
#pragma unroll
    for (int j = 0; j < 16; j++) h[j] = c_upd_b1[j];
#pragma unroll
    for (int i = 0; i < 24; i++)
#pragma unroll
        for (int j = 0; j < 16; j++) h[j] = fmaf(x[i], c_upd_w1[i*16 + j], h[j]);
#pragma unroll
    for (int j = 0; j < 16; j++) h[j] = fast_tanh(h[j]);

    float u[8];
#pragma unroll
    for (int j = 0; j < 8; j++) u[j] = c_upd_b2[j];
#pragma unroll
    for (int i = 0; i < 16; i++)
#pragma unroll
        for (int j = 0; j < 8; j++) u[j] = fmaf(h[i], c_upd_w2[i*8 + j], u[j]);

    float4 r0 = make_float4(softclamp(x[0]+u[0]), softclamp(x[1]+u[1]),
                            softclamp(x[2]+u[2]), softclamp(x[3]+u[3]));
    float4 r1 = make_float4(softclamp(x[4]+u[4]), softclamp(x[5]+u[5]),
                            softclamp(x[6]+u[6]), softclamp(x[7]+u[7]));
    ((float4*)(out_nodes + idx*8))[0] = r0;
    ((float4*)(out_nodes + idx*8))[1] = r1;
}

extern "C" void kernel_launch(void* const* d_in, const int* in_sizes, int n_in,
                              void* d_out, int out_size) {
    (void)in_sizes; (void)n_in; (void)out_size;
    const float* nodes = (const float*)d_in[0];
    const float* edges = (const float*)d_in[1];
    const int*   srcs  = (const int*)d_in[14];
    const int*   tgts  = (const int*)d_in[15];

    cudaMemcpyToSymbolAsync(c_msg_w1, d_in[2],  24*16*sizeof(float), 0, cudaMemcpyDeviceToDevice, 0);
    cudaMemcpyToSymbolAsync(c_msg_b1, d_in[3],  16*sizeof(float),    0, cudaMemcpyDeviceToDevice, 0);
    cudaMemcpyToSymbolAsync(c_msg_w2, d_in[4],  16*24*sizeof(float), 0, cudaMemcpyDeviceToDevice, 0);
    cudaMemcpyToSymbolAsync(c_msg_b2, d_in[5],  24*sizeof(float),    0, cudaMemcpyDeviceToDevice, 0);
    cudaMemcpyToSymbolAsync(c_att_w1, d_in[6],  8*16*sizeof(float),  0, cudaMemcpyDeviceToDevice, 0);
    cudaMemcpyToSymbolAsync(c_att_b1, d_in[7],  16*sizeof(float),    0, cudaMemcpyDeviceToDevice, 0);
    cudaMemcpyToSymbolAsync(c_att_w2, d_in[8],  16*32*sizeof(float), 0, cudaMemcpyDeviceToDevice, 0);
    cudaMemcpyToSymbolAsync(c_att_b2, d_in[9],  32*sizeof(float),    0, cudaMemcpyDeviceToDevice, 0);
    cudaMemcpyToSymbolAsync(c_upd_w1, d_in[10], 24*16*sizeof(float), 0, cudaMemcpyDeviceToDevice, 0);
    cudaMemcpyToSymbolAsync(c_upd_b1, d_in[11], 16*sizeof(float),    0, cudaMemcpyDeviceToDevice, 0);
    cudaMemcpyToSymbolAsync(c_upd_w2, d_in[12], 16*8*sizeof(float),  0, cudaMemcpyDeviceToDevice, 0);
    cudaMemcpyToSymbolAsync(c_upd_b2, d_in[13], 8*sizeof(float),     0, cudaMemcpyDeviceToDevice, 0);

    float* out_nodes = (float*)d_out;
    float* out_edges = out_nodes + (size_t)BB*NN*8;

    dim3 gN((NN + 255)/256, BB);
    node_pre<<<gN, 256>>>(nodes);
    edge_pass<<<NE/128, 128>>>(edges, srcs, tgts, out_edges);
    node_post<<<gN, 256>>>(nodes, out_nodes);
}

// round 12
// speedup vs baseline: 1.1388x; 1.1388x over previous
#include <cuda_runtime.h>
#include <cuda_fp16.h>
#include <math.h>

#define NN 100000
#define NE 1600000
#define BB 2

typedef unsigned long long u64;

// ---------------- constant weights (16B aligned for f32x2 pair reads) ----------------
__constant__ __align__(16) float c_msg_w1[24*16];
__constant__ __align__(16) float c_msg_b1[16];
__constant__ __align__(16) float c_msg_w2[16*24];
__constant__ __align__(16) float c_msg_b2[24];
__constant__ __align__(16) float c_att_w1[8*16];
__constant__ __align__(16) float c_att_b1[16];
__constant__ __align__(16) float c_att_w2[16*32];
__constant__ __align__(16) float c_att_b2[32];
__constant__ __align__(16) float c_upd_w1[24*16];
__constant__ __align__(16) float c_upd_b1[16];
__constant__ __align__(16) float c_upd_w2[16*8];
__constant__ __align__(16) float c_upd_b2[8];

// ---------------- scratch ----------------
// fp16 per-node records, 64B each (4 x 16B chunks of 8 halves):
// src: chunk0 Pa[0:8], chunk1 Pa[8:16], chunk2 a_query, chunk3 a_key
// tgt: chunk0 Pb[0:8], chunk1 Pb[8:16], chunk2 b_key,  chunk3 b_query
__device__ uint4 g_src[(size_t)BB*NN*4];
__device__ uint4 g_tgt[(size_t)BB*NN*4];
// fp16 numerator accumulators: one uint4 (8 halves) per node-side.
__device__ uint4 g_numA[(size_t)BB*NN];
__device__ uint4 g_numB[(size_t)BB*NN];
__device__ float g_denA[(size_t)BB*NN];
__device__ float g_denB[(size_t)BB*NN];

// ---------------- helpers ----------------
__device__ __forceinline__ u64 pack2(float a, float b) {
    u64 r; asm("mov.b64 %0, {%1, %2};" : "=l"(r) : "f"(a), "f"(b)); return r;
}
__device__ __forceinline__ u64 bcast2(float a) { return pack2(a, a); }
__device__ __forceinline__ void unpack2(u64 v, float& a, float& b) {
    asm("mov.b64 {%0, %1}, %2;" : "=f"(a), "=f"(b) : "l"(v));
}
__device__ __forceinline__ u64 fma2(u64 a, u64 b, u64 c) {
    u64 d; asm("fma.rn.f32x2 %0, %1, %2, %3;" : "=l"(d) : "l"(a), "l"(b), "l"(c)); return d;
}
__device__ __forceinline__ float fast_tanh(float x) {
    float y; asm("tanh.approx.f32 %0, %1;" : "=f"(y) : "f"(x)); return y;
}
// Branchless soft_clamp: 1e6*tanh(v*1e-6) ~= v - v*t^2/3 (t=v*1e-6); rel err <1e-13 here.
__device__ __forceinline__ float softclamp(float v) {
    float t = v * 1e-6f;
    return fmaf(-t * t * (1.0f/3.0f), v, v);
}
__device__ __forceinline__ unsigned h2pack(float a, float b) {
    __half2 h = __floats2half2_rn(a, b);
    return *reinterpret_cast<const unsigned*>(&h);
}
__device__ __forceinline__ float2 h2unpack(unsigned u) {
    __half2 h = *reinterpret_cast<const __half2*>(&u);
    return __half22float2(h);
}
// 128-bit half-precision vector reduction: 8 halves in ONE L2 RMW op (sm_90+).
__device__ __forceinline__ void red_f16x8(uint4* ptr, unsigned p0, unsigned p1,
                                          unsigned p2, unsigned p3) {
    asm volatile("red.global.add.noftz.v4.f16x2 [%0], {%1, %2, %3, %4};"
                 :: "l"(ptr), "r"(p0), "r"(p1), "r"(p2), "r"(p3) : "memory");
}

// ================= kernel A: per-node precompute (scalar fp32) + fp16 pack =================
__global__ __launch_bounds__(256) void node_pre(const float* __restrict__ nodes) {
    int n = blockIdx.x * blockDim.x + threadIdx.x;
    if (n >= NN) return;
    size_t idx = (size_t)blockIdx.y * NN + n;

    float x[8];
    float4 v0 = __ldg((const float4*)(nodes + idx*8));
    float4 v1 = __ldg((const float4*)(nodes + idx*8) + 1);
    x[0]=v0.x; x[1]=v0.y; x[2]=v0.z; x[3]=v0.w;
    x[4]=v1.x; x[5]=v1.y; x[6]=v1.z; x[7]=v1.w;

    float pa[16], pb[16], h[16];
#pragma unroll
    for (int j = 0; j < 16; j++) { pa[j] = c_msg_b1[j]; pb[j] = 0.f; h[j] = c_att_b1[j]; }
#pragma unroll
    for (int i = 0; i < 8; i++) {
#pragma unroll
        for (int j = 0; j < 16; j++) {
            pa[j] = fmaf(x[i], c_msg_w1[i*16 + j],     pa[j]);
            pb[j] = fmaf(x[i], c_msg_w1[(8+i)*16 + j], pb[j]);
            h[j]  = fmaf(x[i], c_att_w1[i*16 + j],     h[j]);
        }
    }
#pragma unroll
    for (int j = 0; j < 16; j++) h[j] = fast_tanh(h[j]);

    float att[32];
#pragma unroll
    for (int j = 0; j < 32; j++) att[j] = c_att_b2[j];
#pragma unroll
    for (int i = 0; i < 16; i++)
#pragma unroll
        for (int j = 0; j < 32; j++) att[j] = fmaf(h[i], c_att_w2[i*32 + j], att[j]);

    // att layout (jnp.split): a_key[0:8] a_query[8:16] b_key[16:24] b_query[24:32]
    uint4* sr = g_src + idx*4;
    sr[0] = make_uint4(h2pack(pa[0],pa[1]),  h2pack(pa[2],pa[3]),
                       h2pack(pa[4],pa[5]),  h2pack(pa[6],pa[7]));
    sr[1] = make_uint4(h2pack(pa[8],pa[9]),  h2pack(pa[10],pa[11]),
                       h2pack(pa[12],pa[13]),h2pack(pa[14],pa[15]));
    sr[2] = make_uint4(h2pack(att[8],att[9]),  h2pack(att[10],att[11]),
                       h2pack(att[12],att[13]),h2pack(att[14],att[15]));   // a_query
    sr[3] = make_uint4(h2pack(att[0],att[1]),  h2pack(att[2],att[3]),
                       h2pack(att[4],att[5]),  h2pack(att[6],att[7]));     // a_key

    uint4* tr = g_tgt + idx*4;
    tr[0] = make_uint4(h2pack(pb[0],pb[1]),  h2pack(pb[2],pb[3]),
                       h2pack(pb[4],pb[5]),  h2pack(pb[6],pb[7]));
    tr[1] = make_uint4(h2pack(pb[8],pb[9]),  h2pack(pb[10],pb[11]),
                       h2pack(pb[12],pb[13]),h2pack(pb[14],pb[15]));
    tr[2] = make_uint4(h2pack(att[16],att[17]),h2pack(att[18],att[19]),
                       h2pack(att[20],att[21]),h2pack(att[22],att[23]));   // b_key
    tr[3] = make_uint4(h2pack(att[24],att[25]),h2pack(att[26],att[27]),
                       h2pack(att[28],att[29]),h2pack(att[30],att[31]));   // b_query

    g_denA[idx] = 0.f;
    g_denB[idx] = 0.f;
    uint4 z = make_uint4(0u, 0u, 0u, 0u);
    g_numA[idx] = z;
    g_numB[idx] = z;
}

// ================= kernel B: edge pass, fp16-record SMEM-staged gather + fp16 num atomics ====
// One THREAD = one edge. Atomics per edge: 2 x red.v4.f16x2 (num) + 2 x red.f32 (den)
// = 4 L2 RMW ops (was 6).
__global__ __launch_bounds__(128) void edge_pass(const float* __restrict__ edges,
                                                 const int* __restrict__ srcs,
                                                 const int* __restrict__ tgts,
                                                 float* __restrict__ out_edges) {
    const unsigned FULL = 0xffffffffu;
    __shared__ uint4 st_src[4][32*5];   // 5-uint4 (80B) stride: conflict-free both phases
    __shared__ uint4 st_tgt[4][32*5];

    int w    = threadIdx.x >> 5;
    int lane = threadIdx.x & 31;
    int b    = blockIdx.y;
    int e    = blockIdx.x * 128 + w * 32 + lane;   // NE % 128 == 0

    int s = __ldg(srcs + e);
    int t = __ldg(tgts + e);
    size_t si = (size_t)b*NN + s;
    size_t ti = (size_t)b*NN + t;

    // ---- cooperative staging: 4 iterations x (8 records/side) ----
    int c4   = lane & 3;
    int sub8 = lane >> 2;
#pragma unroll
    for (int g = 0; g < 4; g++) {
        int eg = g*8 + sub8;
        int sg = __shfl_sync(FULL, s, eg);
        int tg = __shfl_sync(FULL, t, eg);
        st_src[w][eg*5 + c4] = __ldg(g_src + ((size_t)b*NN + sg)*4 + c4);
        st_tgt[w][eg*5 + c4] = __ldg(g_tgt + ((size_t)b*NN + tg)*4 + c4);
    }
    __syncwarp();

    uint4 s0 = st_src[w][lane*5+0], s1 = st_src[w][lane*5+1];
    uint4 s2 = st_src[w][lane*5+2], s3 = st_src[w][lane*5+3];
    uint4 t0 = st_tgt[w][lane*5+0], t1 = st_tgt[w][lane*5+1];
    uint4 t2 = st_tgt[w][lane*5+2], t3 = st_tgt[w][lane*5+3];

    // ---- h init = Pa[src] + Pb[tgt] ----
    u64 hp[8];
    {
        float2 a, c2;
        a = h2unpack(s0.x); c2 = h2unpack(t0.x); hp[0] = pack2(a.x+c2.x, a.y+c2.y);
        a = h2unpack(s0.y); c2 = h2unpack(t0.y); hp[1] = pack2(a.x+c2.x, a.y+c2.y);
        a = h2unpack(s0.z); c2 = h2unpack(t0.z); hp[2] = pack2(a.x+c2.x, a.y+c2.y);
        a = h2unpack(s0.w); c2 = h2unpack(t0.w); hp[3] = pack2(a.x+c2.x, a.y+c2.y);
        a = h2unpack(s1.x); c2 = h2unpack(t1.x); hp[4] = pack2(a.x+c2.x, a.y+c2.y);
        a = h2unpack(s1.y); c2 = h2unpack(t1.y); hp[5] = pack2(a.x+c2.x, a.y+c2.y);
        a = h2unpack(s1.z); c2 = h2unpack(t1.z); hp[6] = pack2(a.x+c2.x, a.y+c2.y);
        a = h2unpack(s1.w); c2 = h2unpack(t1.w); hp[7] = pack2(a.x+c2.x, a.y+c2.y);
    }

    // ---- logits ----
    float la = 0.f, lb = 0.f;
    {
        float2 q, k;
        q = h2unpack(s2.x); k = h2unpack(t2.x); la += q.x*k.x + q.y*k.y;
        q = h2unpack(s2.y); k = h2unpack(t2.y); la += q.x*k.x + q.y*k.y;
        q = h2unpack(s2.z); k = h2unpack(t2.z); la += q.x*k.x + q.y*k.y;
        q = h2unpack(s2.w); k = h2unpack(t2.w); la += q.x*k.x + q.y*k.y;
        q = h2unpack(t3.x); k = h2unpack(s3.x); lb += q.x*k.x + q.y*k.y;
        q = h2unpack(t3.y); k = h2unpack(s3.y); lb += q.x*k.x + q.y*k.y;
        q = h2unpack(t3.z); k = h2unpack(s3.z); lb += q.x*k.x + q.y*k.y;
        q = h2unpack(t3.w); k = h2unpack(s3.w); lb += q.x*k.x + q.y*k.y;
    }
    const float scale = 0.3535533905932738f; // 1/sqrt(8)
    float exa = __expf(la * scale);
    float exb = __expf(lb * scale);

    // ---- edge features ----
    size_t eoff = ((size_t)b*NE + e)*8;
    float4 e0 = __ldg((const float4*)(edges + eoff));
    float4 e1 = __ldg((const float4*)(edges + eoff) + 1);
    float x[8] = {e0.x, e0.y, e0.z, e0.w, e1.x, e1.y, e1.z, e1.w};

    // ---- layer 1 (f32x2) ----
    const u64* w1p = (const u64*)c_msg_w1;
#pragma unroll
    for (int i = 0; i < 8; i++) {
        u64 xb = bcast2(x[i]);
#pragma unroll
        for (int j = 0; j < 8; j++)
            hp[j] = fma2(xb, w1p[(16+i)*8 + j], hp[j]);
    }
    float h[16];
#pragma unroll
    for (int j = 0; j < 8; j++) { unpack2(hp[j], h[2*j], h[2*j+1]); }
#pragma unroll
    for (int j = 0; j < 16; j++) h[j] = fast_tanh(h[j]);

    // ---- layer 2 (f32x2) ----
    const u64* w2p = (const u64*)c_msg_w2;
    u64 yp[12];
#pragma unroll
    for (int k = 0; k < 12; k++) yp[k] = ((const u64*)c_msg_b2)[k];
#pragma unroll
    for (int i = 0; i < 16; i++) {
        u64 hb = bcast2(h[i]);
#pragma unroll
        for (int k = 0; k < 12; k++) yp[k] = fma2(hb, w2p[i*12 + k], yp[k]);
    }
    float y[24];
#pragma unroll
    for (int k = 0; k < 12; k++) { unpack2(yp[k], y[2*k], y[2*k+1]); }

    // new_edges = soft_clamp(edges + m_ab)
    float4 o0 = make_float4(softclamp(x[0]+y[16]), softclamp(x[1]+y[17]),
                            softclamp(x[2]+y[18]), softclamp(x[3]+y[19]));
    float4 o1 = make_float4(softclamp(x[4]+y[20]), softclamp(x[5]+y[21]),
                            softclamp(x[6]+y[22]), softclamp(x[7]+y[23]));
    ((float4*)(out_edges + eoff))[0] = o0;
    ((float4*)(out_edges + eoff))[1] = o1;

    // ---- reductions: 4 L2 RMW ops total ----
    atomicAdd(&g_denA[si], exa);
    atomicAdd(&g_denB[ti], exb);
    red_f16x8(&g_numA[si],
              h2pack(exa*y[0], exa*y[1]), h2pack(exa*y[2], exa*y[3]),
              h2pack(exa*y[4], exa*y[5]), h2pack(exa*y[6], exa*y[7]));
    red_f16x8(&g_numB[ti],
              h2pack(exb*y[8],  exb*y[9]),  h2pack(exb*y[10], exb*y[11]),
              h2pack(exb*y[12], exb*y[13]), h2pack(exb*y[14], exb*y[15]));
}

// ================= kernel C: node update (scalar fp32) =================
__global__ __launch_bounds__(256) void node_post(const float* __restrict__ nodes,
                                                 float* __restrict__ out_nodes) {
    int n = blockIdx.x * blockDim.x + threadIdx.x;
    if (n >= NN) return;
    size_t idx = (size_t)blockIdx.y * NN + n;

    float x[24];
    float4 v0 = __ldg((const float4*)(nodes + idx*8));
    float4 v1 = __ldg((const float4*)(nodes + idx*8) + 1);
    x[0]=v0.x; x[1]=v0.y; x[2]=v0.z; x[3]=v0.w;
    x[4]=v1.x; x[5]=v1.y; x[6]=v1.z; x[7]=v1.w;

    float ia = 1.f / (g_denA[idx] + 1e-10f);
    uint4 na = g_numA[idx];
    {
        float2 f;
        f = h2unpack(na.x); x[8]  = f.x*ia; x[9]  = f.y*ia;
        f = h2unpack(na.y); x[10] = f.x*ia; x[11] = f.y*ia;
        f = h2unpack(na.z); x[12] = f.x*ia; x[13] = f.y*ia;
        f = h2unpack(na.w); x[14] = f.x*ia; x[15] = f.y*ia;
    }
    float ib = 1.f / (g_denB[idx] + 1e-10f);
    uint4 nb = g_numB[idx];
    {
        float2 f;
        f = h2unpack(nb.x); x[16] = f.x*ib; x[17] = f.y*ib;
        f = h2unpack(nb.y); x[18] = f.x*ib; x[19] = f.y*ib;
        f = h2unpack(nb.z); x[20] = f.x*ib; x[21] = f.y*ib;
        f = h2unpack(nb.w); x[22] = f.x*ib; x[23] = f.y*ib;
    }

    float h[16];
#pragma unroll
    for (int j = 0; j < 16; j++) h[j] = c_upd_b1[j];
#pragma unroll
    for (int i = 0; i < 24; i++)
#pragma unroll
        for (int j = 0; j < 16; j++) h[j] = fmaf(x[i], c_upd_w1[i*16 + j], h[j]);
#pragma unroll
    for (int j = 0; j < 16; j++) h[j] = fast_tanh(h[j]);

    float u[8];
#pragma unroll
    for (int j = 0; j < 8; j++) u[j] = c_upd_b2[j];
#pragma unroll
    for (int i = 0; i < 16; i++)
#pragma unroll
        for (int j = 0; j < 8; j++) u[j] = fmaf(h[i], c_upd_w2[i*8 + j], u[j]);

    float4 r0 = make_float4(softclamp(x[0]+u[0]), softclamp(x[1]+u[1]),
                            softclamp(x[2]+u[2]), softclamp(x[3]+u[3]));
    float4 r1 = make_float4(softclamp(x[4]+u[4]), softclamp(x[5]+u[5]),
                            softclamp(x[6]+u[6]), softclamp(x[7]+u[7]));
    ((float4*)(out_nodes + idx*8))[0] = r0;
    ((float4*)(out_nodes + idx*8))[1] = r1;
}

extern "C" void kernel_launch(void* const* d_in, const int* in_sizes, int n_in,
                              void* d_out, int out_size) {
    (void)in_sizes; (void)n_in; (void)out_size;
    const float* nodes = (const float*)d_in[0];
    const float* edges = (const float*)d_in[1];
    const int*   srcs  = (const int*)d_in[14];
    const int*   tgts  = (const int*)d_in[15];

    cudaMemcpyToSymbolAsync(c_msg_w1, d_in[2],  24*16*sizeof(float), 0, cudaMemcpyDeviceToDevice, 0);
    cudaMemcpyToSymbolAsync(c_msg_b1, d_in[3],  16*sizeof(float),    0, cudaMemcpyDeviceToDevice, 0);
    cudaMemcpyToSymbolAsync(c_msg_w2, d_in[4],  16*24*sizeof(float), 0, cudaMemcpyDeviceToDevice, 0);
    cudaMemcpyToSymbolAsync(c_msg_b2, d_in[5],  24*sizeof(float),    0, cudaMemcpyDeviceToDevice, 0);
    cudaMemcpyToSymbolAsync(c_att_w1, d_in[6],  8*16*sizeof(float),  0, cudaMemcpyDeviceToDevice, 0);
    cudaMemcpyToSymbolAsync(c_att_b1, d_in[7],  16*sizeof(float),    0, cudaMemcpyDeviceToDevice, 0);
    cudaMemcpyToSymbolAsync(c_att_w2, d_in[8],  16*32*sizeof(float), 0, cudaMemcpyDeviceToDevice, 0);
    cudaMemcpyToSymbolAsync(c_att_b2, d_in[9],  32*sizeof(float),    0, cudaMemcpyDeviceToDevice, 0);
    cudaMemcpyToSymbolAsync(c_upd_w1, d_in[10], 24*16*sizeof(float), 0, cudaMemcpyDeviceToDevice, 0);
    cudaMemcpyToSymbolAsync(c_upd_b1, d_in[11], 16*sizeof(float),    0, cudaMemcpyDeviceToDevice, 0);
    cudaMemcpyToSymbolAsync(c_upd_w2, d_in[12], 16*8*sizeof(float),  0, cudaMemcpyDeviceToDevice, 0);
    cudaMemcpyToSymbolAsync(c_upd_b2, d_in[13], 8*sizeof(float),     0, cudaMemcpyDeviceToDevice, 0);

    float* out_nodes = (float*)d_out;
    float* out_edges = out_nodes + (size_t)BB*NN*8;

    dim3 gN((NN + 255)/256, BB);
    dim3 gE(NE/128, BB);
    node_pre<<<gN, 256>>>(nodes);
    edge_pass<<<gE, 128>>>(edges, srcs, tgts, out_edges);
    node_post<<<gN, 256>>>(nodes, out_nodes);
}

// round 13
// speedup vs baseline: 1.1390x; 1.0002x over previous
#include <cuda_runtime.h>
#include <cuda_fp16.h>
#include <math.h>

#define NN 100000
#define NE 1600000
#define BB 2

typedef unsigned long long u64;

// ---------------- constant weights (16B aligned for f32x2 pair reads) ----------------
__constant__ __align__(16) float c_msg_w1[24*16];
__constant__ __align__(16) float c_msg_b1[16];
__constant__ __align__(16) float c_msg_w2[16*24];
__constant__ __align__(16) float c_msg_b2[24];
__constant__ __align__(16) float c_att_w1[8*16];
__constant__ __align__(16) float c_att_b1[16];
__constant__ __align__(16) float c_att_w2[16*32];
__constant__ __align__(16) float c_att_b2[32];
__constant__ __align__(16) float c_upd_w1[24*16];
__constant__ __align__(16) float c_upd_b1[16];
__constant__ __align__(16) float c_upd_w2[16*8];
__constant__ __align__(16) float c_upd_b2[8];

// ---------------- scratch ----------------
// NODE-MAJOR fp16 records: g_src[node*8 + batch*4 + chunk] (uint4 chunks, 128B/node-side).
// One fetch serves BOTH batches of an edge -> 2 gather sectors per edge-unit.
// chunks: 0 Pa[0:8], 1 Pa[8:16], 2 a_query, 3 a_key   (src side)
//         0 Pb[0:8], 1 Pb[8:16], 2 b_key,   3 b_query (tgt side)
__device__ uint4 g_src[(size_t)NN*8];
__device__ uint4 g_tgt[(size_t)NN*8];
// fp16 numerator accumulators: one uint4 (8 halves) per node-side per batch.
__device__ uint4 g_numA[(size_t)BB*NN];
__device__ uint4 g_numB[(size_t)BB*NN];
__device__ float g_denA[(size_t)BB*NN];
__device__ float g_denB[(size_t)BB*NN];

// ---------------- helpers ----------------
__device__ __forceinline__ u64 pack2(float a, float b) {
    u64 r; asm("mov.b64 %0, {%1, %2};" : "=l"(r) : "f"(a), "f"(b)); return r;
}
__device__ __forceinline__ u64 bcast2(float a) { return pack2(a, a); }
__device__ __forceinline__ void unpack2(u64 v, float& a, float& b) {
    asm("mov.b64 {%0, %1}, %2;" : "=f"(a), "=f"(b) : "l"(v));
}
__device__ __forceinline__ u64 fma2(u64 a, u64 b, u64 c) {
    u64 d; asm("fma.rn.f32x2 %0, %1, %2, %3;" : "=l"(d) : "l"(a), "l"(b), "l"(c)); return d;
}
__device__ __forceinline__ float fast_tanh(float x) {
    float y; asm("tanh.approx.f32 %0, %1;" : "=f"(y) : "f"(x)); return y;
}
// Branchless soft_clamp: 1e6*tanh(v*1e-6) ~= v - v*t^2/3 (t=v*1e-6); rel err <1e-13 here.
__device__ __forceinline__ float softclamp(float v) {
    float t = v * 1e-6f;
    return fmaf(-t * t * (1.0f/3.0f), v, v);
}
__device__ __forceinline__ unsigned h2pack(float a, float b) {
    __half2 h = __floats2half2_rn(a, b);
    return *reinterpret_cast<const unsigned*>(&h);
}
__device__ __forceinline__ float2 h2unpack(unsigned u) {
    __half2 h = *reinterpret_cast<const __half2*>(&u);
    return __half22float2(h);
}
// 128-bit half-precision vector reduction: 8 halves in ONE L2 RMW op (sm_90+).
__device__ __forceinline__ void red_f16x8(uint4* ptr, unsigned p0, unsigned p1,
                                          unsigned p2, unsigned p3) {
    asm volatile("red.global.add.noftz.v4.f16x2 [%0], {%1, %2, %3, %4};"
                 :: "l"(ptr), "r"(p0), "r"(p1), "r"(p2), "r"(p3) : "memory");
}

// ================= kernel A: per-node precompute (scalar fp32) + fp16 node-major pack ======
__global__ __launch_bounds__(256) void node_pre(const float* __restrict__ nodes) {
    int n = blockIdx.x * blockDim.x + threadIdx.x;
    if (n >= NN) return;
    int b = blockIdx.y;
    size_t idx = (size_t)b * NN + n;

    float x[8];
    float4 v0 = __ldg((const float4*)(nodes + idx*8));
    float4 v1 = __ldg((const float4*)(nodes + idx*8) + 1);
    x[0]=v0.x; x[1]=v0.y; x[2]=v0.z; x[3]=v0.w;
    x[4]=v1.x; x[5]=v1.y; x[6]=v1.z; x[7]=v1.w;

    float pa[16], pb[16], h[16];
#pragma unroll
    for (int j = 0; j < 16; j++) { pa[j] = c_msg_b1[j]; pb[j] = 0.f; h[j] = c_att_b1[j]; }
#pragma unroll
    for (int i = 0; i < 8; i++) {
#pragma unroll
        for (int j = 0; j < 16; j++) {
            pa[j] = fmaf(x[i], c_msg_w1[i*16 + j],     pa[j]);
            pb[j] = fmaf(x[i], c_msg_w1[(8+i)*16 + j], pb[j]);
            h[j]  = fmaf(x[i], c_att_w1[i*16 + j],     h[j]);
        }
    }
#pragma unroll
    for (int j = 0; j < 16; j++) h[j] = fast_tanh(h[j]);

    float att[32];
#pragma unroll
    for (int j = 0; j < 32; j++) att[j] = c_att_b2[j];
#pragma unroll
    for (int i = 0; i < 16; i++)
#pragma unroll
        for (int j = 0; j < 32; j++) att[j] = fmaf(h[i], c_att_w2[i*32 + j], att[j]);

    // att layout (jnp.split): a_key[0:8] a_query[8:16] b_key[16:24] b_query[24:32]
    uint4* sr = g_src + (size_t)n*8 + b*4;
    sr[0] = make_uint4(h2pack(pa[0],pa[1]),  h2pack(pa[2],pa[3]),
                       h2pack(pa[4],pa[5]),  h2pack(pa[6],pa[7]));
    sr[1] = make_uint4(h2pack(pa[8],pa[9]),  h2pack(pa[10],pa[11]),
                       h2pack(pa[12],pa[13]),h2pack(pa[14],pa[15]));
    sr[2] = make_uint4(h2pack(att[8],att[9]),  h2pack(att[10],att[11]),
                       h2pack(att[12],att[13]),h2pack(att[14],att[15]));   // a_query
    sr[3] = make_uint4(h2pack(att[0],att[1]),  h2pack(att[2],att[3]),
                       h2pack(att[4],att[5]),  h2pack(att[6],att[7]));     // a_key

    uint4* tr = g_tgt + (size_t)n*8 + b*4;
    tr[0] = make_uint4(h2pack(pb[0],pb[1]),  h2pack(pb[2],pb[3]),
                       h2pack(pb[4],pb[5]),  h2pack(pb[6],pb[7]));
    tr[1] = make_uint4(h2pack(pb[8],pb[9]),  h2pack(pb[10],pb[11]),
                       h2pack(pb[12],pb[13]),h2pack(pb[14],pb[15]));
    tr[2] = make_uint4(h2pack(att[16],att[17]),h2pack(att[18],att[19]),
                       h2pack(att[20],att[21]),h2pack(att[22],att[23]));   // b_key
    tr[3] = make_uint4(h2pack(att[24],att[25]),h2pack(att[26],att[27]),
                       h2pack(att[28],att[29]),h2pack(att[30],att[31]));   // b_query

    g_denA[idx] = 0.f;
    g_denB[idx] = 0.f;
    uint4 z = make_uint4(0u, 0u, 0u, 0u);
    g_numA[idx] = z;
    g_numB[idx] = z;
}

// ================= kernel B: edge pass, both batches per thread, fp16 atomics =============
// Staging fetches each node-side's 128B (both batches) ONCE. Per edge-unit:
// gather 2 sectors + 4 RMW (2x red.v4.f16x2 + 2x red.f32) + stream.
// smem stride 9 uint4: STS writes chunks 0-7 of one record (banks 0,4..28),
// LDS reads lane*9 stride — conflict-free both phases.
__global__ __launch_bounds__(128) void edge_pass(const float* __restrict__ edges,
                                                 const int* __restrict__ srcs,
                                                 const int* __restrict__ tgts,
                                                 float* __restrict__ out_edges) {
    const unsigned FULL = 0xffffffffu;
    __shared__ uint4 st_src[4][32*9];
    __shared__ uint4 st_tgt[4][32*9];

    int w    = threadIdx.x >> 5;
    int lane = threadIdx.x & 31;
    int e    = blockIdx.x * 128 + w * 32 + lane;   // NE % 128 == 0

    int s = __ldg(srcs + e);
    int t = __ldg(tgts + e);

    // ---- cooperative staging: 8 iters x 4 records/side, 8 chunks each ----
    int c8  = lane & 7;
    int sub = lane >> 3;
#pragma unroll
    for (int g = 0; g < 8; g++) {
        int rec = g*4 + sub;
        int sg = __shfl_sync(FULL, s, rec);
        int tg = __shfl_sync(FULL, t, rec);
        st_src[w][rec*9 + c8] = __ldg(g_src + (size_t)sg*8 + c8);
        st_tgt[w][rec*9 + c8] = __ldg(g_tgt + (size_t)tg*8 + c8);
    }
    __syncwarp();

#pragma unroll 1
    for (int b = 0; b < BB; b++) {
        uint4 s0 = st_src[w][lane*9 + b*4 + 0];
        uint4 s1 = st_src[w][lane*9 + b*4 + 1];
        uint4 s2 = st_src[w][lane*9 + b*4 + 2];
        uint4 s3 = st_src[w][lane*9 + b*4 + 3];
        uint4 t0 = st_tgt[w][lane*9 + b*4 + 0];
        uint4 t1 = st_tgt[w][lane*9 + b*4 + 1];
        uint4 t2 = st_tgt[w][lane*9 + b*4 + 2];
        uint4 t3 = st_tgt[w][lane*9 + b*4 + 3];

        // h init = Pa[src] + Pb[tgt]
        u64 hp[8];
        {
            float2 a, c2;
            a = h2unpack(s0.x); c2 = h2unpack(t0.x); hp[0] = pack2(a.x+c2.x, a.y+c2.y);
            a = h2unpack(s0.y); c2 = h2unpack(t0.y); hp[1] = pack2(a.x+c2.x, a.y+c2.y);
            a = h2unpack(s0.z); c2 = h2unpack(t0.z); hp[2] = pack2(a.x+c2.x, a.y+c2.y);
            a = h2unpack(s0.w); c2 = h2unpack(t0.w); hp[3] = pack2(a.x+c2.x, a.y+c2.y);
            a = h2unpack(s1.x); c2 = h2unpack(t1.x); hp[4] = pack2(a.x+c2.x, a.y+c2.y);
            a = h2unpack(s1.y); c2 = h2unpack(t1.y); hp[5] = pack2(a.x+c2.x, a.y+c2.y);
            a = h2unpack(s1.z); c2 = h2unpack(t1.z); hp[6] = pack2(a.x+c2.x, a.y+c2.y);
            a = h2unpack(s1.w); c2 = h2unpack(t1.w); hp[7] = pack2(a.x+c2.x, a.y+c2.y);
        }

        // logits
        float la = 0.f, lb = 0.f;
        {
            float2 q, k;
            q = h2unpack(s2.x); k = h2unpack(t2.x); la += q.x*k.x + q.y*k.y;
            q = h2unpack(s2.y); k = h2unpack(t2.y); la += q.x*k.x + q.y*k.y;
            q = h2unpack(s2.z); k = h2unpack(t2.z); la += q.x*k.x + q.y*k.y;
            q = h2unpack(s2.w); k = h2unpack(t2.w); la += q.x*k.x + q.y*k.y;
            q = h2unpack(t3.x); k = h2unpack(s3.x); lb += q.x*k.x + q.y*k.y;
            q = h2unpack(t3.y); k = h2unpack(s3.y); lb += q.x*k.x + q.y*k.y;
            q = h2unpack(t3.z); k = h2unpack(s3.z); lb += q.x*k.x + q.y*k.y;
            q = h2unpack(t3.w); k = h2unpack(s3.w); lb += q.x*k.x + q.y*k.y;
        }
        const float scale = 0.3535533905932738f; // 1/sqrt(8)
        float exa = __expf(la * scale);
        float exb = __expf(lb * scale);

        // edge features
        size_t eoff = ((size_t)b*NE + e)*8;
        float4 e0 = __ldg((const float4*)(edges + eoff));
        float4 e1 = __ldg((const float4*)(edges + eoff) + 1);
        float x[8] = {e0.x, e0.y, e0.z, e0.w, e1.x, e1.y, e1.z, e1.w};

        // layer 1 (f32x2)
        const u64* w1p = (const u64*)c_msg_w1;
#pragma unroll
        for (int i = 0; i < 8; i++) {
            u64 xb = bcast2(x[i]);
#pragma unroll
            for (int j = 0; j < 8; j++)
                hp[j] = fma2(xb, w1p[(16+i)*8 + j], hp[j]);
        }
        float h[16];
#pragma unroll
        for (int j = 0; j < 8; j++) { unpack2(hp[j], h[2*j], h[2*j+1]); }
#pragma unroll
        for (int j = 0; j < 16; j++) h[j] = fast_tanh(h[j]);

        // layer 2 (f32x2)
        const u64* w2p = (const u64*)c_msg_w2;
        u64 yp[12];
#pragma unroll
        for (int k = 0; k < 12; k++) yp[k] = ((const u64*)c_msg_b2)[k];
#pragma unroll
        for (int i = 0; i < 16; i++) {
            u64 hb = bcast2(h[i]);
#pragma unroll
            for (int k = 0; k < 12; k++) yp[k] = fma2(hb, w2p[i*12 + k], yp[k]);
        }
        float y[24];
#pragma unroll
        for (int k = 0; k < 12; k++) { unpack2(yp[k], y[2*k], y[2*k+1]); }

        // new_edges = soft_clamp(edges + m_ab)
        float4 o0 = make_float4(softclamp(x[0]+y[16]), softclamp(x[1]+y[17]),
                                softclamp(x[2]+y[18]), softclamp(x[3]+y[19]));
        float4 o1 = make_float4(softclamp(x[4]+y[20]), softclamp(x[5]+y[21]),
                                softclamp(x[6]+y[22]), softclamp(x[7]+y[23]));
        ((float4*)(out_edges + eoff))[0] = o0;
        ((float4*)(out_edges + eoff))[1] = o1;

        // reductions: 4 L2 RMW ops per unit
        size_t si = (size_t)b*NN + s;
        size_t ti = (size_t)b*NN + t;
        atomicAdd(&g_denA[si], exa);
        atomicAdd(&g_denB[ti], exb);
        red_f16x8(&g_numA[si],
                  h2pack(exa*y[0], exa*y[1]), h2pack(exa*y[2], exa*y[3]),
                  h2pack(exa*y[4], exa*y[5]), h2pack(exa*y[6], exa*y[7]));
        red_f16x8(&g_numB[ti],
                  h2pack(exb*y[8],  exb*y[9]),  h2pack(exb*y[10], exb*y[11]),
                  h2pack(exb*y[12], exb*y[13]), h2pack(exb*y[14], exb*y[15]));
    }
}

// ================= kernel C: node update (scalar fp32) =================
__global__ __launch_bounds__(256) void node_post(const float* __restrict__ nodes,
                                                 float* __restrict__ out_nodes) {
    int n = blockIdx.x * blockDim.x + threadIdx.x;
    if (n >= NN) return;
    size_t idx = (size_t)blockIdx.y * NN + n;

    float x[24];
    float4 v0 = __ldg((const float4*)(nodes + idx*8));
    float4 v1 = __ldg((const float4*)(nodes + idx*8) + 1);
    x[0]=v0.x; x[1]=v0.y; x[2]=v0.z; x[3]=v0.w;
    x[4]=v1.x; x[5]=v1.y; x[6]=v1.z; x[7]=v1.w;

    float ia = 1.f / (g_denA[idx] + 1e-10f);
    uint4 na = g_numA[idx];
    {
        float2 f;
        f = h2unpack(na.x); x[8]  = f.x*ia; x[9]  = f.y*ia;
        f = h2unpack(na.y); x[10] = f.x*ia; x[11] = f.y*ia;
        f = h2unpack(na.z); x[12] = f.x*ia; x[13] = f.y*ia;
        f = h2unpack(na.w); x[14] = f.x*ia; x[15] = f.y*ia;
    }
    float ib = 1.f / (g_denB[idx] + 1e-10f);
    uint4 nb = g_numB[idx];
    {
        float2 f;
        f = h2unpack(nb.x); x[16] = f.x*ib; x[17] = f.y*ib;
        f = h2unpack(nb.y); x[18] = f.x*ib; x[19] = f.y*ib;
        f = h2unpack(nb.z); x[20] = f.x*ib; x[21] = f.y*ib;
        f = h2unpack(nb.w); x[22] = f.x*ib; x[23] = f.y*ib;
    }

    float h[16];
#pragma unroll
    for (int j = 0; j < 16; j++) h[j] = c_upd_b1[j];
#pragma unroll
    for (int i = 0; i < 24; i++)
#pragma unroll
        for (int j = 0; j < 16; j++) h[j] = fmaf(x[i], c_upd_w1[i*16 + j], h[j]);
#pragma unroll
    for (int j = 0; j < 16; j++) h[j] = fast_tanh(h[j]);

    float u[8];
#pragma unroll
    for (int j = 0; j < 8; j++) u[j] = c_upd_b2[j];
#pragma unroll
    for (int i = 0; i < 16; i++)
#pragma unroll
        for (int j = 0; j < 8; j++) u[j] = fmaf(h[i], c_upd_w2[i*8 + j], u[j]);

    float4 r0 = make_float4(softclamp(x[0]+u[0]), softclamp(x[1]+u[1]),
                            softclamp(x[2]+u[2]), softclamp(x[3]+u[3]));
    float4 r1 = make_float4(softclamp(x[4]+u[4]), softclamp(x[5]+u[5]),
                            softclamp(x[6]+u[6]), softclamp(x[7]+u[7]));
    ((float4*)(out_nodes + idx*8))[0] = r0;
    ((float4*)(out_nodes + idx*8))[1] = r1;
}

extern "C" void kernel_launch(void* const* d_in, const int* in_sizes, int n_in,
                              void* d_out, int out_size) {
    (void)in_sizes; (void)n_in; (void)out_size;
    const float* nodes = (const float*)d_in[0];
    const float* edges = (const float*)d_in[1];
    const int*   srcs  = (const int*)d_in[14];
    const int*   tgts  = (const int*)d_in[15];

    cudaMemcpyToSymbolAsync(c_msg_w1, d_in[2],  24*16*sizeof(float), 0, cudaMemcpyDeviceToDevice, 0);
    cudaMemcpyToSymbolAsync(c_msg_b1, d_in[3],  16*sizeof(float),    0, cudaMemcpyDeviceToDevice, 0);
    cudaMemcpyToSymbolAsync(c_msg_w2, d_in[4],  16*24*sizeof(float), 0, cudaMemcpyDeviceToDevice, 0);
    cudaMemcpyToSymbolAsync(c_msg_b2, d_in[5],  24*sizeof(float),    0, cudaMemcpyDeviceToDevice, 0);
    cudaMemcpyToSymbolAsync(c_att_w1, d_in[6],  8*16*sizeof(float),  0, cudaMemcpyDeviceToDevice, 0);
    cudaMemcpyToSymbolAsync(c_att_b1, d_in[7],  16*sizeof(float),    0, cudaMemcpyDeviceToDevice, 0);
    cudaMemcpyToSymbolAsync(c_att_w2, d_in[8],  16*32*sizeof(float), 0, cudaMemcpyDeviceToDevice, 0);
    cudaMemcpyToSymbolAsync(c_att_b2, d_in[9],  32*sizeof(float),    0, cudaMemcpyDeviceToDevice, 0);
    cudaMemcpyToSymbolAsync(c_upd_w1, d_in[10], 24*16*sizeof(float), 0, cudaMemcpyDeviceToDevice, 0);
    cudaMemcpyToSymbolAsync(c_upd_b1, d_in[11], 16*sizeof(float),    0, cudaMemcpyDeviceToDevice, 0);
    cudaMemcpyToSymbolAsync(c_upd_w2, d_in[12], 16*8*sizeof(float),  0, cudaMemcpyDeviceToDevice, 0);
    cudaMemcpyToSymbolAsync(c_upd_b2, d_in[13], 8*sizeof(float),     0, cudaMemcpyDeviceToDevice, 0);

    float* out_nodes = (float*)d_out;
    float* out_edges = out_nodes + (size_t)BB*NN*8;

    dim3 gN((NN + 255)/256, BB);
    node_pre<<<gN, 256>>>(nodes);
    edge_pass<<<NE/128, 128>>>(edges, srcs, tgts, out_edges);
    node_post<<<gN, 256>>>(nodes, out_nodes);
}